// round 2
// baseline (speedup 1.0000x reference)
#include <cuda_runtime.h>
#include <math.h>

#define B_   16
#define L_   1534
#define C_   16
#define SZ_  512
#define O1_  1023
#define O2_  512
#define EPS_ 1e-3f
#define TO_  8          // output-tile per block in stage 1

// Scratch (no allocations allowed)
__device__ __align__(16) float g_xt[L_ * C_ * B_];        // x transposed: [l][c][b]
__device__ __align__(16) float g_h1t[(O1_ + 1) * B_];     // h1 transposed: [o][b]
__device__ __align__(16) float g_h2t[O2_ * B_];           // h2 transposed: [o][b]
__device__ float g_gate[B_];

// ---------------------------------------------------------------------------
// K0: transpose x[b][l][c] -> xt[l][c][b]
// ---------------------------------------------------------------------------
__global__ void k_transpose(const float* __restrict__ x) {
    int l = blockIdx.x;
    int t = threadIdx.x;           // 256 = B*C
    int b = t >> 4;
    int c = t & 15;
    g_xt[l * 256 + c * 16 + b] = x[(b * L_ + l) * C_ + c];
}

// ---------------------------------------------------------------------------
// K1: h1[o][b] = elu( sum_{s,c} x[b,o+s,c] * W1[o,s,c] + b1[o] )
// Block handles TO_ consecutive o's, all 16 b. 256 threads:
//   rlane = t & 63 splits the 8192-long reduction, b4 = t >> 6 picks 4 batches.
// ---------------------------------------------------------------------------
__global__ void __launch_bounds__(256) k_stage1(const float* __restrict__ W1,
                                                const float* __restrict__ b1) {
    int o0    = blockIdx.x * TO_;
    int t     = threadIdx.x;
    int rlane = t & 63;
    int b4    = t >> 6;            // 0..3 -> batches 4*b4..4*b4+3

    float4 acc[TO_];
#pragma unroll
    for (int o = 0; o < TO_; o++) acc[o] = make_float4(0.f, 0.f, 0.f, 0.f);

    bool full = (o0 + TO_ <= O1_);

    if (full) {
#pragma unroll 2
        for (int k = 0; k < 128; k++) {
            int j = rlane + (k << 6);          // reduction index 0..8191
            int s = j >> 4;
            int c = j & 15;
            const float* xtp = &g_xt[(o0 + s) * 256 + c * 16 + b4 * 4];
#pragma unroll
            for (int o = 0; o < TO_; o++) {
                float  w  = W1[(o0 + o) * (SZ_ * C_) + j];
                float4 xv = *(const float4*)(xtp + o * 256);
                acc[o].x = fmaf(w, xv.x, acc[o].x);
                acc[o].y = fmaf(w, xv.y, acc[o].y);
                acc[o].z = fmaf(w, xv.z, acc[o].z);
                acc[o].w = fmaf(w, xv.w, acc[o].w);
            }
        }
    } else {
        for (int k = 0; k < 128; k++) {
            int j = rlane + (k << 6);
            int s = j >> 4;
            int c = j & 15;
            const float* xtp = &g_xt[(o0 + s) * 256 + c * 16 + b4 * 4];
#pragma unroll
            for (int o = 0; o < TO_; o++) {
                if (o0 + o < O1_) {
                    float  w  = W1[(o0 + o) * (SZ_ * C_) + j];
                    float4 xv = *(const float4*)(xtp + o * 256);
                    acc[o].x = fmaf(w, xv.x, acc[o].x);
                    acc[o].y = fmaf(w, xv.y, acc[o].y);
                    acc[o].z = fmaf(w, xv.z, acc[o].z);
                    acc[o].w = fmaf(w, xv.w, acc[o].w);
                }
            }
        }
    }

    // Warp reduce (32 rlanes per warp; warp's b4 is uniform)
#pragma unroll
    for (int o = 0; o < TO_; o++) {
#pragma unroll
        for (int off = 16; off; off >>= 1) {
            acc[o].x += __shfl_down_sync(0xffffffffu, acc[o].x, off);
            acc[o].y += __shfl_down_sync(0xffffffffu, acc[o].y, off);
            acc[o].z += __shfl_down_sync(0xffffffffu, acc[o].z, off);
            acc[o].w += __shfl_down_sync(0xffffffffu, acc[o].w, off);
        }
    }

    __shared__ float4 part[8][TO_];
    int warp = t >> 5;
    int lane = t & 31;
    if (lane == 0) {
#pragma unroll
        for (int o = 0; o < TO_; o++) part[warp][o] = acc[o];
    }
    __syncthreads();

    if (t < TO_ * 16) {
        int o    = t >> 4;
        int b    = t & 15;
        int bg   = b >> 2;
        int comp = b & 3;
        int oo   = o0 + o;
        if (oo < O1_) {
            float v = ((const float*)&part[2 * bg][o])[comp] +
                      ((const float*)&part[2 * bg + 1][o])[comp];
            float h = v + b1[oo];
            h = (h > 0.f) ? h : expm1f(h);
            g_h1t[oo * 16 + b] = h;
        }
    }
}

// ---------------------------------------------------------------------------
// K2: h2[o][b] = sum_s h1[o+s][b] * W2[o,s] + b2[o]   (o < 512)
// ---------------------------------------------------------------------------
__global__ void __launch_bounds__(256) k_stage2(const float* __restrict__ W2,
                                                const float* __restrict__ b2) {
    int o     = blockIdx.x;
    int t     = threadIdx.x;
    int rlane = t & 63;
    int b4    = t >> 6;

    float4 acc = make_float4(0.f, 0.f, 0.f, 0.f);
#pragma unroll
    for (int k = 0; k < 8; k++) {
        int    s  = rlane + (k << 6);
        float  w  = W2[o * SZ_ + s];
        float4 hv = *(const float4*)&g_h1t[(o + s) * 16 + b4 * 4];
        acc.x = fmaf(w, hv.x, acc.x);
        acc.y = fmaf(w, hv.y, acc.y);
        acc.z = fmaf(w, hv.z, acc.z);
        acc.w = fmaf(w, hv.w, acc.w);
    }

#pragma unroll
    for (int off = 16; off; off >>= 1) {
        acc.x += __shfl_down_sync(0xffffffffu, acc.x, off);
        acc.y += __shfl_down_sync(0xffffffffu, acc.y, off);
        acc.z += __shfl_down_sync(0xffffffffu, acc.z, off);
        acc.w += __shfl_down_sync(0xffffffffu, acc.w, off);
    }

    __shared__ float4 part[8];
    int warp = t >> 5;
    int lane = t & 31;
    if (lane == 0) part[warp] = acc;
    __syncthreads();

    if (t < 16) {
        int b    = t;
        int bg   = b >> 2;
        int comp = b & 3;
        float v  = ((const float*)&part[2 * bg])[comp] +
                   ((const float*)&part[2 * bg + 1])[comp];
        g_h2t[o * 16 + b] = v + b2[o];
    }
}

// ---------------------------------------------------------------------------
// K3: gate[b] = (dot(h2[:,b], Wl) + bl) * sigmoid(dot(h2[:,b], Ws) + bs)
// ---------------------------------------------------------------------------
__global__ void __launch_bounds__(512) k_stage3(const float* __restrict__ Wl,
                                                const float* __restrict__ bl,
                                                const float* __restrict__ Ws,
                                                const float* __restrict__ bs) {
    int b = blockIdx.x;
    int t = threadIdx.x;   // 512

    float hv  = g_h2t[t * 16 + b];
    float al  = hv * Wl[t];
    float as_ = hv * Ws[t];

#pragma unroll
    for (int off = 16; off; off >>= 1) {
        al  += __shfl_down_sync(0xffffffffu, al, off);
        as_ += __shfl_down_sync(0xffffffffu, as_, off);
    }

    __shared__ float sl[16], ss[16];
    int warp = t >> 5;
    int lane = t & 31;
    if (lane == 0) { sl[warp] = al; ss[warp] = as_; }
    __syncthreads();

    if (t == 0) {
        float Lv = 0.f, Sv = 0.f;
#pragma unroll
        for (int w = 0; w < 16; w++) { Lv += sl[w]; Sv += ss[w]; }
        Lv += bl[0];
        Sv += bs[0];
        g_gate[b] = Lv * (1.f / (1.f + expf(-Sv)));
    }
}

// ---------------------------------------------------------------------------
// K4: out[b,l,c] = ((l<L ? x[b,l,c] : 0) + gate[b] - mm[c]) * rsqrt(var[c]+eps)*gamma[c] + beta[c]
// ---------------------------------------------------------------------------
__global__ void __launch_bounds__(256) k_stage4(const float* __restrict__ x,
                                                const float* __restrict__ gamma,
                                                const float* __restrict__ beta,
                                                const float* __restrict__ mm,
                                                const float* __restrict__ mv,
                                                float* __restrict__ out) {
    int idx = blockIdx.x * 256 + threadIdx.x;
    const int total = B_ * (L_ + 1) * C_;
    if (idx >= total) return;

    int c = idx & 15;
    int l = (idx >> 4) % (L_ + 1);
    int b = idx / ((L_ + 1) * C_);

    float xv    = (l < L_) ? x[(b * L_ + l) * C_ + c] : 0.f;
    float scale = rsqrtf(mv[c] + EPS_) * gamma[c];
    out[idx] = (xv + g_gate[b] - mm[c]) * scale + beta[c];
}

// ---------------------------------------------------------------------------
extern "C" void kernel_launch(void* const* d_in, const int* in_sizes, int n_in,
                              void* d_out, int out_size) {
    const float* x     = (const float*)d_in[0];
    const float* W1    = (const float*)d_in[1];
    const float* b1    = (const float*)d_in[2];
    const float* W2    = (const float*)d_in[3];
    const float* b2    = (const float*)d_in[4];
    const float* Wl    = (const float*)d_in[5];
    const float* bl    = (const float*)d_in[6];
    const float* Ws    = (const float*)d_in[7];
    const float* bs    = (const float*)d_in[8];
    const float* gamma = (const float*)d_in[9];
    const float* beta  = (const float*)d_in[10];
    const float* mm    = (const float*)d_in[11];
    const float* mv    = (const float*)d_in[12];
    float* out = (float*)d_out;

    k_transpose<<<L_, 256>>>(x);
    k_stage1<<<(O1_ + TO_ - 1) / TO_, 256>>>(W1, b1);
    k_stage2<<<O2_, 256>>>(W2, b2);
    k_stage3<<<B_, 512>>>(Wl, bl, Ws, bs);
    int total = B_ * (L_ + 1) * C_;
    k_stage4<<<(total + 255) / 256, 256>>>(x, gamma, beta, mm, mv, out);
}

// round 3
// speedup vs baseline: 2.3133x; 2.3133x over previous
#include <cuda_runtime.h>
#include <math.h>

#define B_   16
#define L_   1534
#define C_   16
#define SZ_  512
#define O1_  1023
#define O2_  512
#define EPS_ 1e-3f

// Scratch (no allocations allowed)
__device__ __align__(16) float g_h1t[(O1_ + 1) * B_];   // h1 transposed: [o][b]
__device__ __align__(16) float g_h2t[O2_ * B_];         // h2 transposed: [o][b]
__device__ float g_gate[B_];

// ---------------------------------------------------------------------------
// packed f32x2 helpers (FFMA2 is PTX-only; ptxas won't auto-fuse)
// ---------------------------------------------------------------------------
__device__ __forceinline__ void fma2(unsigned long long& d,
                                     unsigned long long a,
                                     unsigned long long b) {
    asm("fma.rn.f32x2 %0, %1, %2, %0;" : "+l"(d) : "l"(a), "l"(b));
}
__device__ __forceinline__ float2 unpack2(unsigned long long v) {
    float2 r;
    asm("mov.b64 {%0, %1}, %2;" : "=f"(r.x), "=f"(r.y) : "l"(v));
    return r;
}

// ---------------------------------------------------------------------------
// K1: h1[o][b] = elu( sum_{s,c} x[b,o+s,c] * W1[o,s,c] + b1[o] )
//
// Block: 8 consecutive o's (o0 = blk*8), 256 threads.
// Thread t: cq = t&3 (c-quad), rp = (t>>2)&7 (row phase mod 8), bq = t>>5.
// Thread owns batches 2bq, 2bq+1. A warp = one bq: lanes span (rp, cq), so a
// W1 float4 load is 512B contiguous per warp (no broadcast redundancy) and
// the final (c, row-phase) reduction is a pure intra-warp shuffle.
// Row loop: r = o0 + d, d = rp + 8k. Interior d in [8,511] -> all 8 o valid
// with s = d - o in [0,512). k=0 prologue (o<=d), k=64 epilogue (o>rp).
// ---------------------------------------------------------------------------
__global__ void __launch_bounds__(256) k_stage1(const float* __restrict__ x,
                                                const float* __restrict__ W1,
                                                const float* __restrict__ b1) {
    const int t  = threadIdx.x;
    const int cq = t & 3;
    const int rp = (t >> 2) & 7;
    const int bq = t >> 5;
    const int o0 = blockIdx.x * 8;

    const float* px0 = x + ((2 * bq) * L_ + o0 + rp) * 16 + 4 * cq;
    const float* px1 = px0 + L_ * 16;
    const float* pw  = W1 + o0 * (SZ_ * C_) + rp * 16 + 4 * cq;

    // acc[o]: (b0,c01) (b0,c23) (b1,c01) (b1,c23) as packed f32x2
    unsigned long long a00[8], a01[8], a10[8], a11[8];
#pragma unroll
    for (int o = 0; o < 8; o++) { a00[o] = 0ull; a01[o] = 0ull; a10[o] = 0ull; a11[o] = 0ull; }

    const bool full = (o0 + 8 <= O1_);

    // ---- prologue k=0 (d = rp): valid o <= rp ----
    {
        ulonglong2 xv0 = *(const ulonglong2*)px0;
        ulonglong2 xv1 = *(const ulonglong2*)px1;
#pragma unroll
        for (int o = 0; o < 8; o++) {
            if (o <= rp && (full || o0 + o < O1_)) {
                ulonglong2 wv = *(const ulonglong2*)(pw + o * 8176);
                fma2(a00[o], wv.x, xv0.x); fma2(a01[o], wv.y, xv0.y);
                fma2(a10[o], wv.x, xv1.x); fma2(a11[o], wv.y, xv1.y);
            }
        }
        px0 += 128; px1 += 128; pw += 128;
    }

    // ---- interior k=1..63 (d in [8,511]): all 8 o valid ----
    if (full) {
#pragma unroll 2
        for (int k = 1; k < 64; k++) {
            ulonglong2 xv0 = *(const ulonglong2*)px0;
            ulonglong2 xv1 = *(const ulonglong2*)px1;
#pragma unroll
            for (int o = 0; o < 8; o++) {
                ulonglong2 wv = *(const ulonglong2*)(pw + o * 8176);
                fma2(a00[o], wv.x, xv0.x); fma2(a01[o], wv.y, xv0.y);
                fma2(a10[o], wv.x, xv1.x); fma2(a11[o], wv.y, xv1.y);
            }
            px0 += 128; px1 += 128; pw += 128;
        }
    } else {
        for (int k = 1; k < 64; k++) {
            ulonglong2 xv0 = *(const ulonglong2*)px0;
            ulonglong2 xv1 = *(const ulonglong2*)px1;
#pragma unroll
            for (int o = 0; o < 8; o++) {
                if (o0 + o < O1_) {
                    ulonglong2 wv = *(const ulonglong2*)(pw + o * 8176);
                    fma2(a00[o], wv.x, xv0.x); fma2(a01[o], wv.y, xv0.y);
                    fma2(a10[o], wv.x, xv1.x); fma2(a11[o], wv.y, xv1.y);
                }
            }
            px0 += 128; px1 += 128; pw += 128;
        }
    }

    // ---- epilogue k=64 (d = 512+rp): valid o > rp ----
    if (rp < 7 && (o0 + rp + 1) < O1_) {
        ulonglong2 xv0 = *(const ulonglong2*)px0;
        ulonglong2 xv1 = *(const ulonglong2*)px1;
#pragma unroll
        for (int o = 0; o < 8; o++) {
            if (o > rp && (o0 + o) < O1_) {
                ulonglong2 wv = *(const ulonglong2*)(pw + o * 8176);
                fma2(a00[o], wv.x, xv0.x); fma2(a01[o], wv.y, xv0.y);
                fma2(a10[o], wv.x, xv1.x); fma2(a11[o], wv.y, xv1.y);
            }
        }
    }

    // ---- reduce over (cq, rp) = all 32 lanes; warp owns its 2 batches ----
#pragma unroll
    for (int o = 0; o < 8; o++) {
        float2 p0 = unpack2(a00[o]), p1 = unpack2(a01[o]);
        float2 q0 = unpack2(a10[o]), q1 = unpack2(a11[o]);
        float s0 = (p0.x + p0.y) + (p1.x + p1.y);
        float s1 = (q0.x + q0.y) + (q1.x + q1.y);
#pragma unroll
        for (int off = 16; off; off >>= 1) {
            s0 += __shfl_down_sync(0xffffffffu, s0, off);
            s1 += __shfl_down_sync(0xffffffffu, s1, off);
        }
        if ((t & 31) == 0) {
            int og = o0 + o;
            if (og < O1_) {
                float bias = b1[og];
                float h0 = s0 + bias; h0 = (h0 > 0.f) ? h0 : expm1f(h0);
                float h1 = s1 + bias; h1 = (h1 > 0.f) ? h1 : expm1f(h1);
                g_h1t[og * 16 + 2 * bq]     = h0;
                g_h1t[og * 16 + 2 * bq + 1] = h1;
            }
        }
    }
}

// ---------------------------------------------------------------------------
// K2: h2[o][b] = sum_s h1[o+s][b] * W2[o*512+s] + b2[o]
// Block per o; thread t: b = t&15, sp = t>>4 (16 s-phases).
// h1 loads: warp covers 16 b x 2 sp -> 2 contiguous 64B rows per instr.
// ---------------------------------------------------------------------------
__global__ void __launch_bounds__(256) k_stage2(const float* __restrict__ W2,
                                                const float* __restrict__ b2) {
    int o  = blockIdx.x;
    int t  = threadIdx.x;
    int b  = t & 15;
    int sp = t >> 4;

    float acc = 0.f;
#pragma unroll
    for (int k = 0; k < 32; k++) {
        int s = sp + (k << 4);
        acc = fmaf(g_h1t[(o + s) * 16 + b], W2[o * SZ_ + s], acc);
    }

    // within warp: lanes = (sp pair, b); fold the two sp's
    acc += __shfl_down_sync(0xffffffffu, acc, 16);

    __shared__ float part[8][16];
    int warp = t >> 5, lane = t & 31;
    if (lane < 16) part[warp][lane] = acc;
    __syncthreads();

    if (t < 16) {
        float v = 0.f;
#pragma unroll
        for (int w = 0; w < 8; w++) v += part[w][t];
        g_h2t[o * 16 + t] = v + b2[o];
    }
}

// ---------------------------------------------------------------------------
// K3: gate[b] = (dot(h2[:,b], Wl) + bl) * sigmoid(dot(h2[:,b], Ws) + bs)
// ---------------------------------------------------------------------------
__global__ void __launch_bounds__(512) k_stage3(const float* __restrict__ Wl,
                                                const float* __restrict__ bl,
                                                const float* __restrict__ Ws,
                                                const float* __restrict__ bs) {
    int b = blockIdx.x;
    int t = threadIdx.x;   // 512

    float hv  = g_h2t[t * 16 + b];
    float al  = hv * Wl[t];
    float as_ = hv * Ws[t];

#pragma unroll
    for (int off = 16; off; off >>= 1) {
        al  += __shfl_down_sync(0xffffffffu, al, off);
        as_ += __shfl_down_sync(0xffffffffu, as_, off);
    }

    __shared__ float sl[16], ss[16];
    int warp = t >> 5;
    int lane = t & 31;
    if (lane == 0) { sl[warp] = al; ss[warp] = as_; }
    __syncthreads();

    if (t == 0) {
        float Lv = 0.f, Sv = 0.f;
#pragma unroll
        for (int w = 0; w < 16; w++) { Lv += sl[w]; Sv += ss[w]; }
        Lv += bl[0];
        Sv += bs[0];
        g_gate[b] = Lv * (1.f / (1.f + expf(-Sv)));
    }
}

// ---------------------------------------------------------------------------
// K4: out[b,l,c] = ((l<L ? x : 0) + gate[b] - mm[c]) * rsqrt(var[c]+eps)*gamma[c] + beta[c]
// float4-vectorized, fully coalesced.
// ---------------------------------------------------------------------------
__global__ void __launch_bounds__(256) k_stage4(const float* __restrict__ x,
                                                const float* __restrict__ gamma,
                                                const float* __restrict__ beta,
                                                const float* __restrict__ mm,
                                                const float* __restrict__ mv,
                                                float* __restrict__ out) {
    const int TOT4 = B_ * (L_ + 1) * C_ / 4;    // 98304
    int i4 = blockIdx.x * 256 + threadIdx.x;
    if (i4 >= TOT4) return;

    int cq   = i4 & 3;
    int rest = i4 >> 2;                 // b*(L+1) + l
    int l    = rest % (L_ + 1);
    int b    = rest / (L_ + 1);

    float4 xv = make_float4(0.f, 0.f, 0.f, 0.f);
    if (l < L_) xv = *(const float4*)(x + (b * L_ + l) * 16 + 4 * cq);

    float g  = g_gate[b];
    int   c0 = 4 * cq;
    float4 r;
    r.x = (xv.x + g - mm[c0 + 0]) * rsqrtf(mv[c0 + 0] + EPS_) * gamma[c0 + 0] + beta[c0 + 0];
    r.y = (xv.y + g - mm[c0 + 1]) * rsqrtf(mv[c0 + 1] + EPS_) * gamma[c0 + 1] + beta[c0 + 1];
    r.z = (xv.z + g - mm[c0 + 2]) * rsqrtf(mv[c0 + 2] + EPS_) * gamma[c0 + 2] + beta[c0 + 2];
    r.w = (xv.w + g - mm[c0 + 3]) * rsqrtf(mv[c0 + 3] + EPS_) * gamma[c0 + 3] + beta[c0 + 3];

    ((float4*)out)[i4] = r;
}

// ---------------------------------------------------------------------------
extern "C" void kernel_launch(void* const* d_in, const int* in_sizes, int n_in,
                              void* d_out, int out_size) {
    const float* x     = (const float*)d_in[0];
    const float* W1    = (const float*)d_in[1];
    const float* b1    = (const float*)d_in[2];
    const float* W2    = (const float*)d_in[3];
    const float* b2    = (const float*)d_in[4];
    const float* Wl    = (const float*)d_in[5];
    const float* bl    = (const float*)d_in[6];
    const float* Ws    = (const float*)d_in[7];
    const float* bs    = (const float*)d_in[8];
    const float* gamma = (const float*)d_in[9];
    const float* beta  = (const float*)d_in[10];
    const float* mm    = (const float*)d_in[11];
    const float* mv    = (const float*)d_in[12];
    float* out = (float*)d_out;

    k_stage1<<<(O1_ + 7) / 8, 256>>>(x, W1, b1);
    k_stage2<<<O2_, 256>>>(W2, b2);
    k_stage3<<<B_, 512>>>(Wl, bl, Ws, bs);
    k_stage4<<<(B_ * (L_ + 1) * C_ / 4 + 255) / 256, 256>>>(x, gamma, beta, mm, mv, out);
}

// round 4
// speedup vs baseline: 4.0742x; 1.7612x over previous
#include <cuda_runtime.h>
#include <math.h>

#define B_   16
#define L_   1534
#define C_   16
#define SZ_  512
#define O1_  1023
#define O2_  512
#define EPS_ 1e-3f

__device__ __align__(16) float g_h1t[(O1_ + 1) * B_];   // h1 transposed: [o][b]
__device__ __align__(16) float g_h2t[O2_ * B_];         // h2 transposed: [o][b]
__device__ float g_gate[B_];

__device__ __forceinline__ void fma2(unsigned long long& d,
                                     unsigned long long a,
                                     unsigned long long b) {
    asm("fma.rn.f32x2 %0, %1, %2, %0;" : "+l"(d) : "l"(a), "l"(b));
}
__device__ __forceinline__ float2 unpack2(unsigned long long v) {
    float2 r;
    asm("mov.b64 {%0, %1}, %2;" : "=f"(r.x), "=f"(r.y) : "l"(v));
    return r;
}

// ---------------------------------------------------------------------------
// K1: h1[o][b] = elu( sum_{s,c} x[b,o+s,c] * W1[o,s,c] + b1[o] )
//
// Block: 8 o's, 256 threads = 8 warps. warp = kh(2) * 4 + bq(4).
//   lane: cq = lane&3 (c-quad), rp = lane>>2 (row phase 0..7).
// Thread covers no=8 o's x nb=4 batches (b = 4bq..4bq+3), kh splits the
// 65-chunk reduction (d = rp + 8k) into k:[0,32) and k:[32,65).
// acc[o][b] is ONE f32x2 accumulating both c01 and c23 products (all c get
// summed at the end, so mixing c-pairs in one accumulator is fine): 64 regs.
// W1 per-block port traffic = 4x (bq only), x = 1x.
// ---------------------------------------------------------------------------
__global__ void __launch_bounds__(256) k_stage1(const float* __restrict__ x,
                                                const float* __restrict__ W1,
                                                const float* __restrict__ b1) {
    const int t    = threadIdx.x;
    const int lane = t & 31;
    const int warp = t >> 5;
    const int cq   = lane & 3;
    const int rp   = lane >> 2;
    const int bq   = warp & 3;
    const int kh   = warp >> 2;
    const int o0   = blockIdx.x * 8;
    const bool full = (o0 + 8 <= O1_);

    unsigned long long acc[8][4];
#pragma unroll
    for (int o = 0; o < 8; o++)
#pragma unroll
        for (int i = 0; i < 4; i++) acc[o][i] = 0ull;

    const int k_begin = kh ? 32 : 0;

    // pointers positioned at k = k_begin
    const float* px[4];
#pragma unroll
    for (int i = 0; i < 4; i++)
        px[i] = x + ((4 * bq + i) * L_ + o0 + rp) * 16 + 4 * cq + k_begin * 128;
    const float* pw = W1 + o0 * (SZ_ * C_) + rp * 16 + 4 * cq + k_begin * 128;

    // ---- prologue (kh=0 only), k=0, d=rp: valid o <= rp ----
    if (kh == 0) {
        ulonglong2 xv[4];
#pragma unroll
        for (int i = 0; i < 4; i++) xv[i] = *(const ulonglong2*)px[i];
#pragma unroll
        for (int o = 0; o < 8; o++) {
            if (o <= rp && (full || o0 + o < O1_)) {
                ulonglong2 wv = *(const ulonglong2*)(pw + o * 8176);
#pragma unroll
                for (int i = 0; i < 4; i++) {
                    fma2(acc[o][i], wv.x, xv[i].x);
                    fma2(acc[o][i], wv.y, xv[i].y);
                }
            }
        }
#pragma unroll
        for (int i = 0; i < 4; i++) px[i] += 128;
        pw += 128;
    }

    // ---- main loop: kh=0 -> k=1..31 (31 iters); kh=1 -> k=32..63 (32 iters) ----
    const int kcount = kh ? 32 : 31;
    if (full) {
#pragma unroll 1
        for (int k = 0; k < kcount; k++) {
            ulonglong2 xv[4];
#pragma unroll
            for (int i = 0; i < 4; i++) xv[i] = *(const ulonglong2*)px[i];
            ulonglong2 wv[8];
#pragma unroll
            for (int o = 0; o < 8; o++) wv[o] = *(const ulonglong2*)(pw + o * 8176);
#pragma unroll
            for (int o = 0; o < 8; o++)
#pragma unroll
                for (int i = 0; i < 4; i++) {
                    fma2(acc[o][i], wv[o].x, xv[i].x);
                    fma2(acc[o][i], wv[o].y, xv[i].y);
                }
#pragma unroll
            for (int i = 0; i < 4; i++) px[i] += 128;
            pw += 128;
        }
    } else {
#pragma unroll 1
        for (int k = 0; k < kcount; k++) {
            ulonglong2 xv[4];
#pragma unroll
            for (int i = 0; i < 4; i++) xv[i] = *(const ulonglong2*)px[i];
#pragma unroll
            for (int o = 0; o < 8; o++) {
                if (o0 + o < O1_) {
                    ulonglong2 wv = *(const ulonglong2*)(pw + o * 8176);
#pragma unroll
                    for (int i = 0; i < 4; i++) {
                        fma2(acc[o][i], wv.x, xv[i].x);
                        fma2(acc[o][i], wv.y, xv[i].y);
                    }
                }
            }
#pragma unroll
            for (int i = 0; i < 4; i++) px[i] += 128;
            pw += 128;
        }
    }

    // ---- epilogue (kh=1 only), k=64, d=512+rp: valid o > rp ----
    if (kh == 1) {
        int row = o0 + 512 + rp;
        if (row > L_ - 1) row = L_ - 1;     // clamped slots only hit masked o's
        ulonglong2 xv[4];
#pragma unroll
        for (int i = 0; i < 4; i++)
            xv[i] = *(const ulonglong2*)(x + ((4 * bq + i) * L_ + row) * 16 + 4 * cq);
#pragma unroll
        for (int o = 0; o < 8; o++) {
            if (o > rp && (full || o0 + o < O1_)) {
                ulonglong2 wv = *(const ulonglong2*)(pw + o * 8176);
#pragma unroll
                for (int i = 0; i < 4; i++) {
                    fma2(acc[o][i], wv.x, xv[i].x);
                    fma2(acc[o][i], wv.y, xv[i].y);
                }
            }
        }
    }

    // ---- reduction: fold f32x2 -> fold cq (shuffle) -> smem over (rp, kh) ----
    float s[8][4];
#pragma unroll
    for (int o = 0; o < 8; o++)
#pragma unroll
        for (int i = 0; i < 4; i++) {
            float2 p = unpack2(acc[o][i]);
            float v = p.x + p.y;
            v += __shfl_xor_sync(0xffffffffu, v, 1);
            v += __shfl_xor_sync(0xffffffffu, v, 2);
            s[o][i] = v;
        }

    __shared__ float red[64][36];   // contrib (warp*8+rp) x 32 values, padded
    if (cq == 0) {
        int contrib = warp * 8 + rp;
#pragma unroll
        for (int o = 0; o < 8; o++) {
            float4 v4 = make_float4(s[o][0], s[o][1], s[o][2], s[o][3]);
            *(float4*)&red[contrib][o * 4] = v4;
        }
    }
    __syncthreads();

    if (t < 128) {
        int o  = t >> 4;
        int b  = t & 15;
        int bqq = b >> 2;
        int bl  = b & 3;
        float v = 0.f;
#pragma unroll
        for (int k2 = 0; k2 < 2; k2++)
#pragma unroll
            for (int r = 0; r < 8; r++)
                v += red[(k2 * 4 + bqq) * 8 + r][o * 4 + bl];
        int og = o0 + o;
        if (og < O1_) {
            float h = v + b1[og];
            h = (h > 0.f) ? h : expm1f(h);
            g_h1t[og * 16 + b] = h;
        }
    }
}

// ---------------------------------------------------------------------------
// K2: h2[o][b] = sum_s h1[o+s][b] * W2[o*512+s] + b2[o]
// ---------------------------------------------------------------------------
__global__ void __launch_bounds__(256) k_stage2(const float* __restrict__ W2,
                                                const float* __restrict__ b2) {
    int o  = blockIdx.x;
    int t  = threadIdx.x;
    int b  = t & 15;
    int sp = t >> 4;

    float acc = 0.f;
#pragma unroll
    for (int k = 0; k < 32; k++) {
        int s = sp + (k << 4);
        acc = fmaf(g_h1t[(o + s) * 16 + b], W2[o * SZ_ + s], acc);
    }

    acc += __shfl_down_sync(0xffffffffu, acc, 16);

    __shared__ float part[8][16];
    int warp = t >> 5, lane = t & 31;
    if (lane < 16) part[warp][lane] = acc;
    __syncthreads();

    if (t < 16) {
        float v = 0.f;
#pragma unroll
        for (int w = 0; w < 8; w++) v += part[w][t];
        g_h2t[o * 16 + t] = v + b2[o];
    }
}

// ---------------------------------------------------------------------------
// K3: gate[b] = (dot(h2[:,b], Wl) + bl) * sigmoid(dot(h2[:,b], Ws) + bs)
// ---------------------------------------------------------------------------
__global__ void __launch_bounds__(512) k_stage3(const float* __restrict__ Wl,
                                                const float* __restrict__ bl,
                                                const float* __restrict__ Ws,
                                                const float* __restrict__ bs) {
    int b = blockIdx.x;
    int t = threadIdx.x;

    float hv  = g_h2t[t * 16 + b];
    float al  = hv * Wl[t];
    float as_ = hv * Ws[t];

#pragma unroll
    for (int off = 16; off; off >>= 1) {
        al  += __shfl_down_sync(0xffffffffu, al, off);
        as_ += __shfl_down_sync(0xffffffffu, as_, off);
    }

    __shared__ float sl[16], ss[16];
    int warp = t >> 5;
    int lane = t & 31;
    if (lane == 0) { sl[warp] = al; ss[warp] = as_; }
    __syncthreads();

    if (t == 0) {
        float Lv = 0.f, Sv = 0.f;
#pragma unroll
        for (int w = 0; w < 16; w++) { Lv += sl[w]; Sv += ss[w]; }
        Lv += bl[0];
        Sv += bs[0];
        g_gate[b] = Lv * (1.f / (1.f + expf(-Sv)));
    }
}

// ---------------------------------------------------------------------------
// K4: out = ((l<L ? x : 0) + gate[b] - mm[c]) * rsqrt(var[c]+eps)*gamma[c] + beta[c]
// 4 independent float4 per thread (MLP=4). cq invariant across the 4 -> one
// scale/shift float4 per thread.
// ---------------------------------------------------------------------------
__global__ void __launch_bounds__(256) k_stage4(const float* __restrict__ x,
                                                const float* __restrict__ gamma,
                                                const float* __restrict__ beta,
                                                const float* __restrict__ mm,
                                                const float* __restrict__ mv,
                                                float* __restrict__ out) {
    // total float4s = 16*1535*4 = 98304 = 96 blocks * 1024
    int base = blockIdx.x * 1024 + threadIdx.x;
    int cq   = base & 3;
    int c0   = 4 * cq;

    float4 sc, sh;
    sc.x = rsqrtf(mv[c0 + 0] + EPS_) * gamma[c0 + 0];
    sc.y = rsqrtf(mv[c0 + 1] + EPS_) * gamma[c0 + 1];
    sc.z = rsqrtf(mv[c0 + 2] + EPS_) * gamma[c0 + 2];
    sc.w = rsqrtf(mv[c0 + 3] + EPS_) * gamma[c0 + 3];
    sh.x = beta[c0 + 0] - mm[c0 + 0] * sc.x;
    sh.y = beta[c0 + 1] - mm[c0 + 1] * sc.y;
    sh.z = beta[c0 + 2] - mm[c0 + 2] * sc.z;
    sh.w = beta[c0 + 3] - mm[c0 + 3] * sc.w;

    float4 xv[4];
    float  gv[4];
#pragma unroll
    for (int j = 0; j < 4; j++) {
        int i4   = base + j * 256;
        int rest = i4 >> 2;
        int l    = rest % (L_ + 1);
        int b    = rest / (L_ + 1);
        gv[j] = g_gate[b];
        xv[j] = make_float4(0.f, 0.f, 0.f, 0.f);
        if (l < L_) xv[j] = *(const float4*)(x + (b * L_ + l) * 16 + 4 * cq);
    }
#pragma unroll
    for (int j = 0; j < 4; j++) {
        int i4 = base + j * 256;
        float4 r;
        r.x = (xv[j].x + gv[j]) * sc.x + sh.x;
        r.y = (xv[j].y + gv[j]) * sc.y + sh.y;
        r.z = (xv[j].z + gv[j]) * sc.z + sh.z;
        r.w = (xv[j].w + gv[j]) * sc.w + sh.w;
        ((float4*)out)[i4] = r;
    }
}

// ---------------------------------------------------------------------------
extern "C" void kernel_launch(void* const* d_in, const int* in_sizes, int n_in,
                              void* d_out, int out_size) {
    const float* x     = (const float*)d_in[0];
    const float* W1    = (const float*)d_in[1];
    const float* b1    = (const float*)d_in[2];
    const float* W2    = (const float*)d_in[3];
    const float* b2    = (const float*)d_in[4];
    const float* Wl    = (const float*)d_in[5];
    const float* bl    = (const float*)d_in[6];
    const float* Ws    = (const float*)d_in[7];
    const float* bs    = (const float*)d_in[8];
    const float* gamma = (const float*)d_in[9];
    const float* beta  = (const float*)d_in[10];
    const float* mm    = (const float*)d_in[11];
    const float* mv    = (const float*)d_in[12];
    float* out = (float*)d_out;

    k_stage1<<<(O1_ + 7) / 8, 256>>>(x, W1, b1);
    k_stage2<<<O2_, 256>>>(W2, b2);
    k_stage3<<<B_, 512>>>(Wl, bl, Ws, bs);
    k_stage4<<<96, 256>>>(x, gamma, beta, mm, mv, out);
}